// round 10
// baseline (speedup 1.0000x reference)
#include <cuda_runtime.h>
#include <math.h>
#include <stdint.h>

#define NB 8
#define NT 2048
#define NC 1024
#define NH 64
#define QSCALE 0.125f   // 64^-0.5
#define NTILES (NT / 64) // 32

// Scratch for projections.
__device__ float g_q[NB * NT * NH];
__device__ float g_k[NB * NT * NH];
__device__ float g_v[NB * NT * NH];

// ============================================================================
// Packed f32x2 helpers (family-level PTX, sm_100+; no 'a' suffix needed)
// ============================================================================
__device__ __forceinline__ void fma2(uint64_t& d, uint64_t a, uint64_t b) {
    asm("fma.rn.f32x2 %0, %1, %2, %0;" : "+l"(d) : "l"(a), "l"(b));
}
__device__ __forceinline__ void mul2(uint64_t& d, uint64_t a) {
    asm("mul.rn.f32x2 %0, %0, %1;" : "+l"(d) : "l"(a));
}
__device__ __forceinline__ uint64_t pack2(float x, float y) {
    uint64_t r;
    asm("mov.b64 %0, {%1, %2};" : "=l"(r)
        : "r"(__float_as_uint(x)), "r"(__float_as_uint(y)));
    return r;
}
__device__ __forceinline__ float2 unpack2(uint64_t p) {
    uint32_t lo, hi;
    asm("mov.b64 {%0, %1}, %2;" : "=r"(lo), "=r"(hi) : "l"(p));
    return make_float2(__uint_as_float(lo), __uint_as_float(hi));
}

// ============================================================================
// Fused projection GEMM: {q,k,v} = x @ {wq,wk,wv}
// M = 16384, K = 1024, N = 192. Block tile 128x192, thread tile 8x12 (f32x2).
// A stored DUPLICATED in smem so dup operands load directly as 64-bit pairs.
// ============================================================================
#define PBK 16
#define PA2 264   // pitch of duplicated A rows (2*128 + 8), 16B-aligned
#define PBP 196

struct ProjSmem {
    float a2[2][PBK][PA2];   // a2[kk][2r] = a2[kk][2r+1] = x val (dup)
    float b [2][PBK][PBP];   // b[kk][col], col 0..191
};

extern __shared__ char proj_smem_raw[];

__global__ __launch_bounds__(256) void proj_kernel(
    const float* __restrict__ x,
    const float* __restrict__ wq,
    const float* __restrict__ wk,
    const float* __restrict__ wv)
{
    ProjSmem* ps = reinterpret_cast<ProjSmem*>(proj_smem_raw);

    const int m0  = blockIdx.x * 128;
    const int tid = threadIdx.x;
    const int tr  = tid >> 4;      // rows tr*8..tr*8+7
    const int tc  = tid & 15;      // cols tc*12..tc*12+11

    const float* wsel[3] = {wq, wk, wv};
    float*       dsel[3] = {g_q, g_k, g_v};

    uint64_t accP[8][6];           // [row][colpair], lanes = (col 2jp, 2jp+1)
    #pragma unroll
    for (int i = 0; i < 8; i++)
        #pragma unroll
        for (int j = 0; j < 6; j++) accP[i][j] = 0ull;

    float4 ar[2], br[3];
    #pragma unroll
    for (int u = 0; u < 2; u++) {
        int f = tid * 2 + u;
        int r = f >> 2, c4 = f & 3;
        ar[u] = *(const float4*)&x[(size_t)(m0 + r) * NC + c4 * 4];
    }
    #pragma unroll
    for (int u = 0; u < 3; u++) {
        int f  = tid * 3 + u;
        int kk = f / 48, c4 = f % 48;
        int col = c4 * 4;
        br[u] = *(const float4*)&wsel[col >> 6][(size_t)kk * NH + (col & 63)];
    }
    #pragma unroll
    for (int u = 0; u < 2; u++) {
        int f = tid * 2 + u;
        int r = f >> 2, c4 = f & 3;
        float vv[4] = {ar[u].x, ar[u].y, ar[u].z, ar[u].w};
        #pragma unroll
        for (int e = 0; e < 4; e++)
            *(float2*)&ps->a2[0][c4 * 4 + e][2 * r] = make_float2(vv[e], vv[e]);
    }
    #pragma unroll
    for (int u = 0; u < 3; u++) {
        int f  = tid * 3 + u;
        int kk = f / 48, c4 = f % 48;
        *(float4*)&ps->b[0][kk][c4 * 4] = br[u];
    }
    __syncthreads();

    const int NSTEP = NC / PBK;
    for (int ks = 0; ks < NSTEP; ks++) {
        int cur = ks & 1;
        if (ks + 1 < NSTEP) {
            int k0 = (ks + 1) * PBK;
            #pragma unroll
            for (int u = 0; u < 2; u++) {
                int f = tid * 2 + u;
                int r = f >> 2, c4 = f & 3;
                ar[u] = *(const float4*)&x[(size_t)(m0 + r) * NC + k0 + c4 * 4];
            }
            #pragma unroll
            for (int u = 0; u < 3; u++) {
                int f  = tid * 3 + u;
                int kk = f / 48, c4 = f % 48;
                int col = c4 * 4;
                br[u] = *(const float4*)&wsel[col >> 6][(size_t)(k0 + kk) * NH + (col & 63)];
            }
        }
        #pragma unroll
        for (int kk = 0; kk < PBK; kk++) {
            ulonglong2 a01 = *(const ulonglong2*)&ps->a2[cur][kk][tr * 16];
            ulonglong2 a23 = *(const ulonglong2*)&ps->a2[cur][kk][tr * 16 + 4];
            ulonglong2 a45 = *(const ulonglong2*)&ps->a2[cur][kk][tr * 16 + 8];
            ulonglong2 a67 = *(const ulonglong2*)&ps->a2[cur][kk][tr * 16 + 12];
            uint64_t aD[8] = {a01.x, a01.y, a23.x, a23.y,
                              a45.x, a45.y, a67.x, a67.y};
            ulonglong2 b01 = *(const ulonglong2*)&ps->b[cur][kk][tc * 12];
            ulonglong2 b23 = *(const ulonglong2*)&ps->b[cur][kk][tc * 12 + 4];
            ulonglong2 b45 = *(const ulonglong2*)&ps->b[cur][kk][tc * 12 + 8];
            uint64_t bP[6] = {b01.x, b01.y, b23.x, b23.y, b45.x, b45.y};
            #pragma unroll
            for (int i = 0; i < 8; i++)
                #pragma unroll
                for (int j = 0; j < 6; j++)
                    fma2(accP[i][j], aD[i], bP[j]);
        }
        if (ks + 1 < NSTEP) {
            int nxt = cur ^ 1;
            #pragma unroll
            for (int u = 0; u < 2; u++) {
                int f = tid * 2 + u;
                int r = f >> 2, c4 = f & 3;
                float vv[4] = {ar[u].x, ar[u].y, ar[u].z, ar[u].w};
                #pragma unroll
                for (int e = 0; e < 4; e++)
                    *(float2*)&ps->a2[nxt][c4 * 4 + e][2 * r] = make_float2(vv[e], vv[e]);
            }
            #pragma unroll
            for (int u = 0; u < 3; u++) {
                int f  = tid * 3 + u;
                int kk = f / 48, c4 = f % 48;
                *(float4*)&ps->b[nxt][kk][c4 * 4] = br[u];
            }
        }
        __syncthreads();
    }

    #pragma unroll
    for (int i = 0; i < 8; i++) {
        int r = m0 + tr * 8 + i;
        #pragma unroll
        for (int g = 0; g < 3; g++) {
            int col = tc * 12 + g * 4;
            float* dst = dsel[col >> 6];
            float2 t0 = unpack2(accP[i][2 * g]);
            float2 t1 = unpack2(accP[i][2 * g + 1]);
            *(float4*)&dst[(size_t)r * NH + (col & 63)] =
                make_float4(t0.x, t0.y, t1.x, t1.y);
        }
    }
}

// ============================================================================
// Causal flash attention v5: R3 structure (pair (p,31-p), double-buffered KV,
// 1 barrier/tile) + f32x2 math. K and V stored duplicated; P staged transposed.
// grid = (16, 8), 256 threads.
// ============================================================================
#define AP  68    // pitch for qT / sT (16B-aligned rows)
#define AP2 136   // pitch for duplicated kT2 / v2

struct AttnSmem {
    float qT [64][AP];        // qT[h][row], pre-scaled by QSCALE
    float kT2[2][64][AP2];    // kT2[h][2c] = kT2[h][2c+1] = K[c][h]
    float v2 [2][64][AP2];    // v2[t][2h]  = v2[t][2h+1]  = V[t][h]
    float sT [64][AP];        // P transposed: sT[col][row]
};

extern __shared__ char attn_smem_raw[];

__device__ __forceinline__ void attn_tile(
    AttnSmem* sm, const float* Qb, const float* Kb, const float* Vb,
    float* out, int b, int it, int tid, int ty, int tx)
{
    // ---- load Q tile transposed, pre-scaled ----
    #pragma unroll
    for (int u = 0; u < 4; u++) {
        int f  = tid * 4 + u;
        int r  = f >> 4;
        int c4 = f & 15;
        float4 t = *(const float4*)&Qb[(size_t)(it * 64 + r) * NH + c4 * 4];
        sm->qT[c4 * 4 + 0][r] = t.x * QSCALE;
        sm->qT[c4 * 4 + 1][r] = t.y * QSCALE;
        sm->qT[c4 * 4 + 2][r] = t.z * QSCALE;
        sm->qT[c4 * 4 + 3][r] = t.w * QSCALE;
    }
    // ---- KV tile 0 into buffer 0 (duplicated stores) ----
    #pragma unroll
    for (int u = 0; u < 4; u++) {
        int f  = tid * 4 + u;
        int r  = f >> 4;
        int c4 = f & 15;
        size_t gb = (size_t)r * NH + c4 * 4;
        float4 tk = *(const float4*)&Kb[gb];
        float4 tv = *(const float4*)&Vb[gb];
        float kv[4] = {tk.x, tk.y, tk.z, tk.w};
        float vv[4] = {tv.x, tv.y, tv.z, tv.w};
        #pragma unroll
        for (int e = 0; e < 4; e++) {
            *(float2*)&sm->kT2[0][c4 * 4 + e][2 * r] = make_float2(kv[e], kv[e]);
            *(float2*)&sm->v2 [0][r][2 * (c4 * 4 + e)] = make_float2(vv[e], vv[e]);
        }
    }
    __syncthreads();

    uint64_t oP[2][4];       // rows (2p, 2p+1) x col j
    float m[4], l[4];
    #pragma unroll
    for (int p = 0; p < 2; p++)
        #pragma unroll
        for (int j = 0; j < 4; j++) oP[p][j] = 0ull;
    #pragma unroll
    for (int i = 0; i < 4; i++) { m[i] = -INFINITY; l[i] = 0.f; }

    for (int jt = 0; jt <= it; jt++) {
        int cur = jt & 1;
        float4 kr[4], vr[4];
        if (jt < it) {
            #pragma unroll
            for (int u = 0; u < 4; u++) {
                int f  = tid * 4 + u;
                int r  = f >> 4;
                int c4 = f & 15;
                size_t gb = (size_t)((jt + 1) * 64 + r) * NH + c4 * 4;
                kr[u] = *(const float4*)&Kb[gb];
                vr[u] = *(const float4*)&Vb[gb];
            }
        }

        // ---- S = Q @ K^T (packed over row pairs) ----
        uint64_t accP[2][4];
        #pragma unroll
        for (int p = 0; p < 2; p++)
            #pragma unroll
            for (int j = 0; j < 4; j++) accP[p][j] = 0ull;
        #pragma unroll
        for (int kk = 0; kk < 64; kk++) {
            ulonglong2 ap  = *(const ulonglong2*)&sm->qT[kk][ty * 4];
            ulonglong2 b01 = *(const ulonglong2*)&sm->kT2[cur][kk][tx * 8];
            ulonglong2 b23 = *(const ulonglong2*)&sm->kT2[cur][kk][tx * 8 + 4];
            uint64_t aP[2] = {ap.x, ap.y};
            uint64_t bD[4] = {b01.x, b01.y, b23.x, b23.y};
            #pragma unroll
            for (int p = 0; p < 2; p++)
                #pragma unroll
                for (int j = 0; j < 4; j++)
                    fma2(accP[p][j], aP[p], bD[j]);
        }

        // ---- unpack to scalars ----
        float acc[4][4];
        #pragma unroll
        for (int p = 0; p < 2; p++)
            #pragma unroll
            for (int j = 0; j < 4; j++) {
                float2 t = unpack2(accP[p][j]);
                acc[2 * p    ][j] = t.x;
                acc[2 * p + 1][j] = t.y;
            }

        if (jt == it) {
            #pragma unroll
            for (int i = 0; i < 4; i++) {
                int qi = ty * 4 + i;
                #pragma unroll
                for (int j = 0; j < 4; j++)
                    if (tx * 4 + j > qi) acc[i][j] = -INFINITY;
            }
        }

        // ---- online softmax ----
        float alpha[4], pr[4][4];
        #pragma unroll
        for (int i = 0; i < 4; i++) {
            float v = fmaxf(fmaxf(acc[i][0], acc[i][1]),
                            fmaxf(acc[i][2], acc[i][3]));
            #pragma unroll
            for (int d = 1; d < 16; d <<= 1)
                v = fmaxf(v, __shfl_xor_sync(0xffffffffu, v, d));
            float mn = fmaxf(m[i], v);
            alpha[i] = __expf(m[i] - mn);
            m[i] = mn;
            float rs = 0.f;
            #pragma unroll
            for (int j = 0; j < 4; j++) {
                pr[i][j] = __expf(acc[i][j] - mn);
                rs += pr[i][j];
            }
            #pragma unroll
            for (int d = 1; d < 16; d <<= 1)
                rs += __shfl_xor_sync(0xffffffffu, rs, d);
            l[i] = l[i] * alpha[i] + rs;
        }
        // scale O by alpha (packed)
        uint64_t alphaP[2] = {pack2(alpha[0], alpha[1]), pack2(alpha[2], alpha[3])};
        #pragma unroll
        for (int p = 0; p < 2; p++)
            #pragma unroll
            for (int j = 0; j < 4; j++) mul2(oP[p][j], alphaP[p]);

        // ---- stage P transposed (half-warp local) ----
        #pragma unroll
        for (int j = 0; j < 4; j++)
            *(float4*)&sm->sT[tx * 4 + j][ty * 4] =
                make_float4(pr[0][j], pr[1][j], pr[2][j], pr[3][j]);
        __syncwarp();

        // ---- O += P @ V (packed) ----
        #pragma unroll
        for (int kk = 0; kk < 64; kk++) {
            ulonglong2 pp  = *(const ulonglong2*)&sm->sT[kk][ty * 4];
            ulonglong2 v01 = *(const ulonglong2*)&sm->v2[cur][kk][tx * 8];
            ulonglong2 v23 = *(const ulonglong2*)&sm->v2[cur][kk][tx * 8 + 4];
            uint64_t pP[2] = {pp.x, pp.y};
            uint64_t vD[4] = {v01.x, v01.y, v23.x, v23.y};
            #pragma unroll
            for (int p = 0; p < 2; p++)
                #pragma unroll
                for (int j = 0; j < 4; j++)
                    fma2(oP[p][j], pP[p], vD[j]);
        }

        // ---- store prefetched KV into other buffer ----
        if (jt < it) {
            int nxt = cur ^ 1;
            #pragma unroll
            for (int u = 0; u < 4; u++) {
                int f  = tid * 4 + u;
                int r  = f >> 4;
                int c4 = f & 15;
                float kv[4] = {kr[u].x, kr[u].y, kr[u].z, kr[u].w};
                float vv[4] = {vr[u].x, vr[u].y, vr[u].z, vr[u].w};
                #pragma unroll
                for (int e = 0; e < 4; e++) {
                    *(float2*)&sm->kT2[nxt][c4 * 4 + e][2 * r] = make_float2(kv[e], kv[e]);
                    *(float2*)&sm->v2 [nxt][r][2 * (c4 * 4 + e)] = make_float2(vv[e], vv[e]);
                }
            }
        }
        __syncthreads();
    }

    // ---- normalize and write ----
    #pragma unroll
    for (int p = 0; p < 2; p++) {
        float2 row0[4], row1[4];
        #pragma unroll
        for (int j = 0; j < 4; j++) {
            float2 t = unpack2(oP[p][j]);
            row0[j] = make_float2(t.x, 0.f);
            row1[j] = make_float2(t.y, 0.f);
        }
        float inv0 = 1.f / l[2 * p];
        float inv1 = 1.f / l[2 * p + 1];
        size_t r0 = (size_t)b * NT + it * 64 + ty * 4 + 2 * p;
        size_t r1 = r0 + 1;
        *(float4*)&out[r0 * NH + tx * 4] =
            make_float4(row0[0].x * inv0, row0[1].x * inv0,
                        row0[2].x * inv0, row0[3].x * inv0);
        *(float4*)&out[r1 * NH + tx * 4] =
            make_float4(row1[0].x * inv1, row1[1].x * inv1,
                        row1[2].x * inv1, row1[3].x * inv1);
    }
}

__global__ __launch_bounds__(256) void attn_kernel(float* __restrict__ out)
{
    AttnSmem* sm = reinterpret_cast<AttnSmem*>(attn_smem_raw);

    const int b   = blockIdx.y;
    const int p   = blockIdx.x;
    const int tid = threadIdx.x;
    const int ty  = tid >> 4;
    const int tx  = tid & 15;

    const float* Qb = g_q + (size_t)b * NT * NH;
    const float* Kb = g_k + (size_t)b * NT * NH;
    const float* Vb = g_v + (size_t)b * NT * NH;

    attn_tile(sm, Qb, Kb, Vb, out, b, NTILES - 1 - p, tid, ty, tx);
    __syncthreads();
    attn_tile(sm, Qb, Kb, Vb, out, b, p, tid, ty, tx);
}

// ---------------------------------------------------------------------------

extern "C" void kernel_launch(void* const* d_in, const int* in_sizes, int n_in,
                              void* d_out, int out_size)
{
    const float* x  = (const float*)d_in[0];
    const float* wq = (const float*)d_in[1];
    const float* wk = (const float*)d_in[2];
    const float* wv = (const float*)d_in[3];
    float* out = (float*)d_out;

    const int proj_smem = (int)sizeof(ProjSmem);
    cudaFuncSetAttribute(proj_kernel,
                         cudaFuncAttributeMaxDynamicSharedMemorySize,
                         proj_smem);
    const int attn_smem = (int)sizeof(AttnSmem);
    cudaFuncSetAttribute(attn_kernel,
                         cudaFuncAttributeMaxDynamicSharedMemorySize,
                         attn_smem);

    proj_kernel<<<dim3((NB * NT) / 128), 256, proj_smem>>>(x, wq, wk, wv);
    attn_kernel<<<dim3(NTILES / 2, NB), 256, attn_smem>>>(out);
}

// round 11
// speedup vs baseline: 1.6126x; 1.6126x over previous
#include <cuda_runtime.h>
#include <math.h>
#include <stdint.h>

#define NB 8
#define NT 2048
#define NC 1024
#define NH 64
#define QSCALE 0.125f    // 64^-0.5
#define NTILES (NT / 64) // 32
#define SPLIT_MIN 16     // tiles with it >= 16 split KV into 2 halves
#define NITEMS (NB * 48) // 8 * (16 singles + 32 halves) = 384

// Scratch for projections.
__device__ float g_q[NB * NT * NH];
__device__ float g_k[NB * NT * NH];
__device__ float g_v[NB * NT * NH];

// Split-KV partials: slot = (b*32 + it)*2 + half
__device__ float g_po[NB * NTILES * 2 * 64 * NH];  // unnormalized O
__device__ float g_pm[NB * NTILES * 2 * 64];       // row max
__device__ float g_pl[NB * NTILES * 2 * 64];       // row sum
__device__ int   g_items[NITEMS * 4];              // b, it, kv0, kv1
__device__ int   g_counter;

// ---------------------------------------------------------------------------
// Fused projection GEMM (proven R4 version): {q,k,v} = x @ {wq,wk,wv}
// ---------------------------------------------------------------------------
#define PBK 16
#define PAP 132
#define PBP 196

__global__ __launch_bounds__(256) void proj_kernel(
    const float* __restrict__ x,
    const float* __restrict__ wq,
    const float* __restrict__ wk,
    const float* __restrict__ wv)
{
    __shared__ float sA[2][PBK][PAP];
    __shared__ float sB[2][PBK][PBP];

    const int m0  = blockIdx.x * 128;
    const int tid = threadIdx.x;
    const int tr  = tid >> 4;
    const int tc  = tid & 15;

    const float* wsel[3] = {wq, wk, wv};
    float*       dsel[3] = {g_q, g_k, g_v};

    float acc[8][12];
    #pragma unroll
    for (int i = 0; i < 8; i++)
        #pragma unroll
        for (int j = 0; j < 12; j++) acc[i][j] = 0.f;

    float4 ar[2], br[3];
    #pragma unroll
    for (int u = 0; u < 2; u++) {
        int f = tid * 2 + u;
        int r = f >> 2, c4 = f & 3;
        ar[u] = *(const float4*)&x[(size_t)(m0 + r) * NC + c4 * 4];
    }
    #pragma unroll
    for (int u = 0; u < 3; u++) {
        int f  = tid * 3 + u;
        int kk = f / 48, c4 = f % 48;
        int col = c4 * 4;
        br[u] = *(const float4*)&wsel[col >> 6][(size_t)kk * NH + (col & 63)];
    }
    #pragma unroll
    for (int u = 0; u < 2; u++) {
        int f = tid * 2 + u;
        int r = f >> 2, c4 = f & 3;
        sA[0][c4 * 4 + 0][r] = ar[u].x;
        sA[0][c4 * 4 + 1][r] = ar[u].y;
        sA[0][c4 * 4 + 2][r] = ar[u].z;
        sA[0][c4 * 4 + 3][r] = ar[u].w;
    }
    #pragma unroll
    for (int u = 0; u < 3; u++) {
        int f  = tid * 3 + u;
        int kk = f / 48, c4 = f % 48;
        *(float4*)&sB[0][kk][c4 * 4] = br[u];
    }
    __syncthreads();

    const int NSTEP = NC / PBK;
    for (int ks = 0; ks < NSTEP; ks++) {
        int cur = ks & 1;
        if (ks + 1 < NSTEP) {
            int k0 = (ks + 1) * PBK;
            #pragma unroll
            for (int u = 0; u < 2; u++) {
                int f = tid * 2 + u;
                int r = f >> 2, c4 = f & 3;
                ar[u] = *(const float4*)&x[(size_t)(m0 + r) * NC + k0 + c4 * 4];
            }
            #pragma unroll
            for (int u = 0; u < 3; u++) {
                int f  = tid * 3 + u;
                int kk = f / 48, c4 = f % 48;
                int col = c4 * 4;
                br[u] = *(const float4*)&wsel[col >> 6][(size_t)(k0 + kk) * NH + (col & 63)];
            }
        }
        #pragma unroll
        for (int kk = 0; kk < PBK; kk++) {
            float a[8], b[12];
            *(float4*)&a[0] = *(float4*)&sA[cur][kk][tr * 8];
            *(float4*)&a[4] = *(float4*)&sA[cur][kk][tr * 8 + 4];
            *(float4*)&b[0] = *(float4*)&sB[cur][kk][tc * 12];
            *(float4*)&b[4] = *(float4*)&sB[cur][kk][tc * 12 + 4];
            *(float4*)&b[8] = *(float4*)&sB[cur][kk][tc * 12 + 8];
            #pragma unroll
            for (int i = 0; i < 8; i++)
                #pragma unroll
                for (int j = 0; j < 12; j++)
                    acc[i][j] = fmaf(a[i], b[j], acc[i][j]);
        }
        if (ks + 1 < NSTEP) {
            int nxt = cur ^ 1;
            #pragma unroll
            for (int u = 0; u < 2; u++) {
                int f = tid * 2 + u;
                int r = f >> 2, c4 = f & 3;
                sA[nxt][c4 * 4 + 0][r] = ar[u].x;
                sA[nxt][c4 * 4 + 1][r] = ar[u].y;
                sA[nxt][c4 * 4 + 2][r] = ar[u].z;
                sA[nxt][c4 * 4 + 3][r] = ar[u].w;
            }
            #pragma unroll
            for (int u = 0; u < 3; u++) {
                int f  = tid * 3 + u;
                int kk = f / 48, c4 = f % 48;
                *(float4*)&sB[nxt][kk][c4 * 4] = br[u];
            }
        }
        __syncthreads();
    }

    #pragma unroll
    for (int i = 0; i < 8; i++) {
        int r = m0 + tr * 8 + i;
        #pragma unroll
        for (int g = 0; g < 3; g++) {
            int col = tc * 12 + g * 4;
            float* dst = dsel[col >> 6];
            float4 t = make_float4(acc[i][g*4+0], acc[i][g*4+1],
                                   acc[i][g*4+2], acc[i][g*4+3]);
            *(float4*)&dst[(size_t)r * NH + (col & 63)] = t;
        }
    }
}

// ---------------------------------------------------------------------------
// Work-list construction: 384 items, LPT (descending size) order.
// ---------------------------------------------------------------------------
__device__ __forceinline__ void decode_item(int e, int& b, int& it,
                                            int& kv0, int& kv1)
{
    b = e / 48;
    int r = e - b * 48;
    if (r < SPLIT_MIN) {            // single-piece small tiles (it 0..15)
        it = r; kv0 = 0; kv1 = it + 1;
    } else {                        // halves of tiles it 16..31
        int j = r - SPLIT_MIN;      // 0..31
        it = SPLIT_MIN + (j >> 1);
        int half = j & 1;
        int mid = (it + 1) >> 1;
        kv0 = half ? mid : 0;
        kv1 = half ? (it + 1) : mid;
    }
}

__global__ void init_kernel()
{
    int e = blockIdx.x * 256 + threadIdx.x;
    if (e == 0) g_counter = 0;
    if (e >= NITEMS) return;

    int b, it, kv0, kv1;
    decode_item(e, b, it, kv0, kv1);
    int sz = kv1 - kv0;

    int rank = 0;
    for (int f = 0; f < NITEMS; f++) {
        int fb, fit, fkv0, fkv1;
        decode_item(f, fb, fit, fkv0, fkv1);
        int fsz = fkv1 - fkv0;
        rank += (fsz > sz) || (fsz == sz && f < e);
    }
    g_items[rank * 4 + 0] = b;
    g_items[rank * 4 + 1] = it;
    g_items[rank * 4 + 2] = kv0;
    g_items[rank * 4 + 3] = kv1;
}

// ---------------------------------------------------------------------------
// Persistent causal flash attention with split-KV work queue.
// Inner loop = proven R3 structure. 256 threads, 2 CTAs/SM.
// ---------------------------------------------------------------------------
#define PITCH 68
struct AttnSmem {
    float qT[64][PITCH];
    float kT[2][64][PITCH];
    float v [2][64][PITCH];
    float s [64][PITCH];
    int   slot;
};

extern __shared__ char attn_smem_raw[];

__device__ __forceinline__ void attn_item(
    AttnSmem* sm, int b, int it, int kv0, int kv1, int tid, int ty, int tx)
{
    const float* Qb = g_q + (size_t)b * NT * NH;
    const float* Kb = g_k + (size_t)b * NT * NH;
    const float* Vb = g_v + (size_t)b * NT * NH;

    // ---- load Q tile transposed, pre-scaled ----
    #pragma unroll
    for (int u = 0; u < 4; u++) {
        int f  = tid * 4 + u;
        int r  = f >> 4;
        int c4 = f & 15;
        float4 t = *(const float4*)&Qb[(size_t)(it * 64 + r) * NH + c4 * 4];
        sm->qT[c4 * 4 + 0][r] = t.x * QSCALE;
        sm->qT[c4 * 4 + 1][r] = t.y * QSCALE;
        sm->qT[c4 * 4 + 2][r] = t.z * QSCALE;
        sm->qT[c4 * 4 + 3][r] = t.w * QSCALE;
    }
    // ---- first KV tile into buffer 0 ----
    #pragma unroll
    for (int u = 0; u < 4; u++) {
        int f  = tid * 4 + u;
        int r  = f >> 4;
        int c4 = f & 15;
        size_t gb = (size_t)(kv0 * 64 + r) * NH + c4 * 4;
        float4 tk = *(const float4*)&Kb[gb];
        float4 tv = *(const float4*)&Vb[gb];
        sm->kT[0][c4 * 4 + 0][r] = tk.x;
        sm->kT[0][c4 * 4 + 1][r] = tk.y;
        sm->kT[0][c4 * 4 + 2][r] = tk.z;
        sm->kT[0][c4 * 4 + 3][r] = tk.w;
        *(float4*)&sm->v[0][r][c4 * 4] = tv;
    }
    __syncthreads();

    float o[4][4];
    float m[4], l[4];
    #pragma unroll
    for (int i = 0; i < 4; i++) {
        m[i] = -INFINITY; l[i] = 0.f;
        #pragma unroll
        for (int j = 0; j < 4; j++) o[i][j] = 0.f;
    }

    for (int jt = kv0; jt < kv1; jt++) {
        int cur = (jt - kv0) & 1;
        float4 kr[4], vr[4];
        if (jt + 1 < kv1) {
            #pragma unroll
            for (int u = 0; u < 4; u++) {
                int f  = tid * 4 + u;
                int r  = f >> 4;
                int c4 = f & 15;
                size_t gb = (size_t)((jt + 1) * 64 + r) * NH + c4 * 4;
                kr[u] = *(const float4*)&Kb[gb];
                vr[u] = *(const float4*)&Vb[gb];
            }
        }

        float acc[4][4];
        #pragma unroll
        for (int i = 0; i < 4; i++)
            #pragma unroll
            for (int j = 0; j < 4; j++) acc[i][j] = 0.f;
        #pragma unroll
        for (int kk = 0; kk < 64; kk++) {
            float4 a = *(float4*)&sm->qT[kk][ty * 4];
            float4 bb = *(float4*)&sm->kT[cur][kk][tx * 4];
            float av[4] = {a.x, a.y, a.z, a.w};
            float bv[4] = {bb.x, bb.y, bb.z, bb.w};
            #pragma unroll
            for (int i = 0; i < 4; i++)
                #pragma unroll
                for (int j = 0; j < 4; j++)
                    acc[i][j] = fmaf(av[i], bv[j], acc[i][j]);
        }

        if (jt == it) {
            #pragma unroll
            for (int i = 0; i < 4; i++) {
                int qi = ty * 4 + i;
                #pragma unroll
                for (int j = 0; j < 4; j++)
                    if (tx * 4 + j > qi) acc[i][j] = -INFINITY;
            }
        }

        float mn[4], alpha[4];
        #pragma unroll
        for (int i = 0; i < 4; i++) {
            float v = fmaxf(fmaxf(acc[i][0], acc[i][1]),
                            fmaxf(acc[i][2], acc[i][3]));
            #pragma unroll
            for (int d = 1; d < 16; d <<= 1)
                v = fmaxf(v, __shfl_xor_sync(0xffffffffu, v, d));
            mn[i] = fmaxf(m[i], v);
            alpha[i] = __expf(m[i] - mn[i]);
            m[i] = mn[i];
        }
        #pragma unroll
        for (int i = 0; i < 4; i++) {
            float p0 = __expf(acc[i][0] - mn[i]);
            float p1 = __expf(acc[i][1] - mn[i]);
            float p2 = __expf(acc[i][2] - mn[i]);
            float p3 = __expf(acc[i][3] - mn[i]);
            *(float4*)&sm->s[ty * 4 + i][tx * 4] = make_float4(p0, p1, p2, p3);
            float rs = (p0 + p1) + (p2 + p3);
            #pragma unroll
            for (int d = 1; d < 16; d <<= 1)
                rs += __shfl_xor_sync(0xffffffffu, rs, d);
            l[i] = l[i] * alpha[i] + rs;
            #pragma unroll
            for (int j = 0; j < 4; j++) o[i][j] *= alpha[i];
        }
        __syncwarp();

        #pragma unroll
        for (int kk = 0; kk < 64; kk++) {
            float p[4];
            #pragma unroll
            for (int i = 0; i < 4; i++) p[i] = sm->s[ty * 4 + i][kk];
            float4 vv4 = *(float4*)&sm->v[cur][kk][tx * 4];
            float vv[4] = {vv4.x, vv4.y, vv4.z, vv4.w};
            #pragma unroll
            for (int i = 0; i < 4; i++)
                #pragma unroll
                for (int j = 0; j < 4; j++)
                    o[i][j] = fmaf(p[i], vv[j], o[i][j]);
        }

        if (jt + 1 < kv1) {
            int nxt = cur ^ 1;
            #pragma unroll
            for (int u = 0; u < 4; u++) {
                int f  = tid * 4 + u;
                int r  = f >> 4;
                int c4 = f & 15;
                sm->kT[nxt][c4 * 4 + 0][r] = kr[u].x;
                sm->kT[nxt][c4 * 4 + 1][r] = kr[u].y;
                sm->kT[nxt][c4 * 4 + 2][r] = kr[u].z;
                sm->kT[nxt][c4 * 4 + 3][r] = kr[u].w;
                *(float4*)&sm->v[nxt][r][c4 * 4] = vr[u];
            }
        }
        __syncthreads();
    }

    // ---- write unnormalized partials ----
    const int hf   = (kv0 > 0) ? 1 : 0;
    const int slot = ((b * NTILES) + it) * 2 + hf;
    float* po = g_po + (size_t)slot * 64 * NH;
    #pragma unroll
    for (int i = 0; i < 4; i++) {
        int r = ty * 4 + i;
        if (tx == 0) {
            g_pm[slot * 64 + r] = m[i];
            g_pl[slot * 64 + r] = l[i];
        }
        *(float4*)&po[(size_t)r * NH + tx * 4] =
            make_float4(o[i][0], o[i][1], o[i][2], o[i][3]);
    }
}

__global__ __launch_bounds__(256, 2) void attn_kernel()
{
    AttnSmem* sm = reinterpret_cast<AttnSmem*>(attn_smem_raw);
    const int tid = threadIdx.x;
    const int ty  = tid >> 4;
    const int tx  = tid & 15;

    for (;;) {
        if (tid == 0) sm->slot = atomicAdd(&g_counter, 1);
        __syncthreads();
        int slot = sm->slot;
        __syncthreads();
        if (slot >= NITEMS) return;

        int b   = g_items[slot * 4 + 0];
        int it  = g_items[slot * 4 + 1];
        int kv0 = g_items[slot * 4 + 2];
        int kv1 = g_items[slot * 4 + 3];

        attn_item(sm, b, it, kv0, kv1, tid, ty, tx);
        __syncthreads();
    }
}

// ---------------------------------------------------------------------------
// Merge partials -> final output. One thread per query row.
// ---------------------------------------------------------------------------
__global__ void merge_kernel(float* __restrict__ out)
{
    int row = blockIdx.x * 256 + threadIdx.x;   // 0 .. NB*NT-1
    if (row >= NB * NT) return;
    int b  = row >> 11;
    int t  = row & (NT - 1);
    int it = t >> 6;
    int r  = t & 63;

    int slot0 = ((b * NTILES) + it) * 2;
    const float* po0 = g_po + (size_t)slot0 * 64 * NH + (size_t)r * NH;

    if (it < SPLIT_MIN) {
        float inv = 1.f / g_pl[slot0 * 64 + r];
        #pragma unroll
        for (int c = 0; c < NH / 4; c++) {
            float4 v = *(const float4*)&po0[c * 4];
            *(float4*)&out[(size_t)row * NH + c * 4] =
                make_float4(v.x * inv, v.y * inv, v.z * inv, v.w * inv);
        }
    } else {
        int slot1 = slot0 + 1;
        const float* po1 = g_po + (size_t)slot1 * 64 * NH + (size_t)r * NH;
        float m0 = g_pm[slot0 * 64 + r];
        float m1 = g_pm[slot1 * 64 + r];
        float M  = fmaxf(m0, m1);
        float a0 = __expf(m0 - M);
        float a1 = __expf(m1 - M);
        float inv = 1.f / (a0 * g_pl[slot0 * 64 + r] + a1 * g_pl[slot1 * 64 + r]);
        #pragma unroll
        for (int c = 0; c < NH / 4; c++) {
            float4 v0 = *(const float4*)&po0[c * 4];
            float4 v1 = *(const float4*)&po1[c * 4];
            *(float4*)&out[(size_t)row * NH + c * 4] = make_float4(
                (a0 * v0.x + a1 * v1.x) * inv,
                (a0 * v0.y + a1 * v1.y) * inv,
                (a0 * v0.z + a1 * v1.z) * inv,
                (a0 * v0.w + a1 * v1.w) * inv);
        }
    }
}

// ---------------------------------------------------------------------------

extern "C" void kernel_launch(void* const* d_in, const int* in_sizes, int n_in,
                              void* d_out, int out_size)
{
    const float* x  = (const float*)d_in[0];
    const float* wq = (const float*)d_in[1];
    const float* wk = (const float*)d_in[2];
    const float* wv = (const float*)d_in[3];
    float* out = (float*)d_out;

    const int attn_smem = (int)sizeof(AttnSmem);
    cudaFuncSetAttribute(attn_kernel,
                         cudaFuncAttributeMaxDynamicSharedMemorySize,
                         attn_smem);

    proj_kernel<<<dim3((NB * NT) / 128), 256>>>(x, wq, wk, wv);
    init_kernel<<<2, 256>>>();
    attn_kernel<<<296, 256, attn_smem>>>();
    merge_kernel<<<(NB * NT + 255) / 256, 256>>>(out);
}